// round 2
// baseline (speedup 1.0000x reference)
#include <cuda_runtime.h>
#include <math.h>

#define B_SZ   4096
#define IN_SZ  1024
#define HID_SZ 2048
#define OUT_SZ 512

// scratch: rate transposed [HID][BATCH] (m-contiguous rows)
__device__ float g_Rt[(size_t)HID_SZ * B_SZ];

__device__ __forceinline__ unsigned long long pack2(float x, float y) {
    unsigned long long r;
    asm("mov.b64 %0, {%1, %2};" : "=l"(r) : "f"(x), "f"(y));
    return r;
}
__device__ __forceinline__ void unpack2(unsigned long long p, float& x, float& y) {
    asm("mov.b64 {%0, %1}, %2;" : "=f"(x), "=f"(y) : "l"(p));
}
__device__ __forceinline__ void ffma2(unsigned long long& c, unsigned long long a, unsigned long long b) {
    asm("fma.rn.f32x2 %0, %1, %2, %0;" : "+l"(c) : "l"(a), "l"(b));
}

// GEMM1: Rt[n][m] = 0.35*sigmoid((6/7)*(sum_k psp[k][m]*W_h[n][k] + b_h[n]))
// A = psp [IN][B] (m contiguous), B = W_h [HID][IN] (k contiguous)
__global__ __launch_bounds__(256, 2)
void k_hidden(const float* __restrict__ A, const float* __restrict__ Bw,
              const float* __restrict__ bias)
{
    __shared__ float As[8][128];
    __shared__ float Bs[8][128];
    const int m0 = blockIdx.x * 128;
    const int n0 = blockIdx.y * 128;
    const int tid = threadIdx.x;
    const int tx = tid & 15;   // n group (8 cols)
    const int ty = tid >> 4;   // m group (8 rows)
    const int a_k = tid >> 5, a_m = (tid & 31) << 2;
    const int b_n = tid >> 1, b_k = (tid & 1) << 2;
    const float* Ap = A + (size_t)a_k * B_SZ + m0 + a_m;
    const float* Bp = Bw + (size_t)(n0 + b_n) * IN_SZ + b_k;

    unsigned long long c2[4][8];
#pragma unroll
    for (int i = 0; i < 4; i++)
#pragma unroll
        for (int j = 0; j < 8; j++) c2[i][j] = 0ull;

    for (int k0 = 0; k0 < IN_SZ; k0 += 8) {
        const float4 av = *(const float4*)(Ap + (size_t)k0 * B_SZ);
        const float4 bv = *(const float4*)(Bp + k0);
        *(float4*)&As[a_k][a_m] = av;
        Bs[b_k + 0][b_n] = bv.x;
        Bs[b_k + 1][b_n] = bv.y;
        Bs[b_k + 2][b_n] = bv.z;
        Bs[b_k + 3][b_n] = bv.w;
        __syncthreads();
#pragma unroll
        for (int k = 0; k < 8; k++) {
            const ulonglong2 ua0 = *(const ulonglong2*)&As[k][ty * 8];
            const ulonglong2 ua1 = *(const ulonglong2*)&As[k][ty * 8 + 4];
            const float4 bv0 = *(const float4*)&Bs[k][tx * 8];
            const float4 bv1 = *(const float4*)&Bs[k][tx * 8 + 4];
            unsigned long long a2[4];
            a2[0] = ua0.x; a2[1] = ua0.y; a2[2] = ua1.x; a2[3] = ua1.y;
            unsigned long long bb[8];
            bb[0] = pack2(bv0.x, bv0.x); bb[1] = pack2(bv0.y, bv0.y);
            bb[2] = pack2(bv0.z, bv0.z); bb[3] = pack2(bv0.w, bv0.w);
            bb[4] = pack2(bv1.x, bv1.x); bb[5] = pack2(bv1.y, bv1.y);
            bb[6] = pack2(bv1.z, bv1.z); bb[7] = pack2(bv1.w, bv1.w);
#pragma unroll
            for (int i = 0; i < 4; i++)
#pragma unroll
                for (int j = 0; j < 8; j++) ffma2(c2[i][j], a2[i], bb[j]);
        }
        __syncthreads();
    }

    const float s = 6.0f / 7.0f;
    const float4 bias0 = *(const float4*)&bias[n0 + tx * 8];
    const float4 bias1 = *(const float4*)&bias[n0 + tx * 8 + 4];
    const float bvals[8] = {bias0.x, bias0.y, bias0.z, bias0.w,
                            bias1.x, bias1.y, bias1.z, bias1.w};
#pragma unroll
    for (int j = 0; j < 8; j++) {
        const int n = n0 + tx * 8 + j;
        const float bb = bvals[j];
        float r[8];
#pragma unroll
        for (int i = 0; i < 4; i++) {
            float x, y;
            unpack2(c2[i][j], x, y);
            const float vx = s * (x + bb);
            const float vy = s * (y + bb);
            r[2 * i]     = 0.35f / (1.0f + expf(-vx));
            r[2 * i + 1] = 0.35f / (1.0f + expf(-vy));
        }
        float* dst = g_Rt + (size_t)n * B_SZ + m0 + ty * 8;
        *(float4*)dst       = *(const float4*)&r[0];
        *(float4*)(dst + 4) = *(const float4*)&r[4];
    }
}

// GEMM2: out[m][n] = 0.35*sigmoid(0.75*(sum_h Rt[h][m]*W_o[n][h]) + 0.75*b_o[n] + 0.125*label[m][n])
// A = g_Rt [HID][B] (m contiguous), B = W_o [OUT][HID] (k contiguous)
__global__ __launch_bounds__(256, 2)
void k_out(const float* __restrict__ Bw, const float* __restrict__ bias,
           const float* __restrict__ label, float* __restrict__ out)
{
    __shared__ float As[8][128];
    __shared__ float Bs[8][64];
    const int m0 = blockIdx.x * 128;
    const int n0 = blockIdx.y * 64;
    const int tid = threadIdx.x;
    const int tx = tid & 15;   // n group (4 cols)
    const int ty = tid >> 4;   // m group (8 rows)
    const int a_k = tid >> 5, a_m = (tid & 31) << 2;
    const int b_n = tid >> 2, b_k = (tid & 3) << 1;
    const float* Ap = g_Rt + (size_t)a_k * B_SZ + m0 + a_m;
    const float* Bp = Bw + (size_t)(n0 + b_n) * HID_SZ + b_k;

    unsigned long long c2[4][4];
#pragma unroll
    for (int i = 0; i < 4; i++)
#pragma unroll
        for (int j = 0; j < 4; j++) c2[i][j] = 0ull;

    for (int k0 = 0; k0 < HID_SZ; k0 += 8) {
        const float4 av = *(const float4*)(Ap + (size_t)k0 * B_SZ);
        const float2 bv = *(const float2*)(Bp + k0);
        *(float4*)&As[a_k][a_m] = av;
        Bs[b_k + 0][b_n] = bv.x;
        Bs[b_k + 1][b_n] = bv.y;
        __syncthreads();
#pragma unroll
        for (int k = 0; k < 8; k++) {
            const ulonglong2 ua0 = *(const ulonglong2*)&As[k][ty * 8];
            const ulonglong2 ua1 = *(const ulonglong2*)&As[k][ty * 8 + 4];
            const float4 bv0 = *(const float4*)&Bs[k][tx * 4];
            unsigned long long a2[4];
            a2[0] = ua0.x; a2[1] = ua0.y; a2[2] = ua1.x; a2[3] = ua1.y;
            unsigned long long bb[4];
            bb[0] = pack2(bv0.x, bv0.x); bb[1] = pack2(bv0.y, bv0.y);
            bb[2] = pack2(bv0.z, bv0.z); bb[3] = pack2(bv0.w, bv0.w);
#pragma unroll
            for (int i = 0; i < 4; i++)
#pragma unroll
                for (int j = 0; j < 4; j++) ffma2(c2[i][j], a2[i], bb[j]);
        }
        __syncthreads();
    }

    // unpack accumulators: c[m_local][n_local]
    float c[8][4];
#pragma unroll
    for (int i = 0; i < 4; i++)
#pragma unroll
        for (int j = 0; j < 4; j++)
            unpack2(c2[i][j], c[2 * i][j], c[2 * i + 1][j]);

    const float4 bo = *(const float4*)&bias[n0 + tx * 4];
    const float bo75[4] = {0.75f * bo.x, 0.75f * bo.y, 0.75f * bo.z, 0.75f * bo.w};
#pragma unroll
    for (int i = 0; i < 8; i++) {
        const int m = m0 + ty * 8 + i;
        const float4 lb = *(const float4*)&label[(size_t)m * OUT_SZ + n0 + tx * 4];
        float v[4];
        v[0] = 0.75f * c[i][0] + bo75[0] + 0.125f * lb.x;
        v[1] = 0.75f * c[i][1] + bo75[1] + 0.125f * lb.y;
        v[2] = 0.75f * c[i][2] + bo75[2] + 0.125f * lb.z;
        v[3] = 0.75f * c[i][3] + bo75[3] + 0.125f * lb.w;
        float4 o;
        o.x = 0.35f / (1.0f + expf(-v[0]));
        o.y = 0.35f / (1.0f + expf(-v[1]));
        o.z = 0.35f / (1.0f + expf(-v[2]));
        o.w = 0.35f / (1.0f + expf(-v[3]));
        *(float4*)&out[(size_t)m * OUT_SZ + n0 + tx * 4] = o;
    }
}

extern "C" void kernel_launch(void* const* d_in, const int* in_sizes, int n_in,
                              void* d_out, int out_size) {
    const float* psp   = (const float*)d_in[0];  // [1024, 4096]
    const float* label = (const float*)d_in[1];  // [4096, 512]
    const float* W_h   = (const float*)d_in[2];  // [2048, 1024]
    const float* b_h   = (const float*)d_in[3];  // [2048]
    const float* W_o   = (const float*)d_in[4];  // [512, 2048]
    const float* b_o   = (const float*)d_in[5];  // [512]
    float* out = (float*)d_out;                  // [4096, 512]

    k_hidden<<<dim3(B_SZ / 128, HID_SZ / 128), 256>>>(psp, W_h, b_h);
    k_out<<<dim3(B_SZ / 128, OUT_SZ / 64), 256>>>(W_o, b_o, label, out);
}

// round 4
// speedup vs baseline: 5.6348x; 5.6348x over previous
#include <cuda_runtime.h>
#include <cuda_fp16.h>
#include <cstdint>

#define B_SZ   4096
#define IN_SZ  1024
#define HID_SZ 2048
#define OUT_SZ 512

// ---------------- scratch (device globals; no allocation) ----------------
__device__ __align__(128) __half g_At[(size_t)B_SZ * IN_SZ];    // psp^T  [B][IN]  fp16
__device__ __align__(128) __half g_Wh[(size_t)HID_SZ * IN_SZ];  // W_h    [HID][IN]
__device__ __align__(128) __half g_Wo[(size_t)OUT_SZ * HID_SZ]; // W_o    [OUT][HID]
__device__ __align__(128) __half g_R [(size_t)B_SZ * HID_SZ];   // rate   [B][HID]

// ---------------- helpers ----------------
__device__ __forceinline__ uint32_t su32(const void* p) {
    uint32_t a;
    asm("{ .reg .u64 t; cvta.to.shared.u64 t, %1; cvt.u32.u64 %0, t; }" : "=r"(a) : "l"(p));
    return a;
}
__device__ __forceinline__ void cp16(uint32_t s, const void* g) {
    asm volatile("cp.async.cg.shared.global [%0], [%1], 16;" :: "r"(s), "l"(g));
}
#define CP_COMMIT()  asm volatile("cp.async.commit_group;")
#define CP_WAIT(N)   asm volatile("cp.async.wait_group %0;" :: "n"(N))

#define LDSM4(r, addr) \
    asm volatile("ldmatrix.sync.aligned.m8n8.x4.shared.b16 {%0,%1,%2,%3}, [%4];" \
        : "=r"((r)[0]), "=r"((r)[1]), "=r"((r)[2]), "=r"((r)[3]) : "r"(addr))

#define MMA(d, a, b0, b1) \
    asm volatile("mma.sync.aligned.m16n8k16.row.col.f32.f16.f16.f32 " \
        "{%0,%1,%2,%3},{%4,%5,%6,%7},{%8,%9},{%0,%1,%2,%3};" \
        : "+f"((d)[0]), "+f"((d)[1]), "+f"((d)[2]), "+f"((d)[3]) \
        : "r"((a)[0]), "r"((a)[1]), "r"((a)[2]), "r"((a)[3]), "r"(b0), "r"(b1))

// swizzled byte offset inside an [rows][32] fp16 tile (64B rows, 16B chunks)
__device__ __forceinline__ uint32_t swoff(int row, int ch) {
    return (uint32_t)(row * 64 + ((ch ^ ((row >> 1) & 3)) << 4));
}

// ---------------- fused GEMM: D[128,128] tile of A[M,K] x B[N,K]^T ----------------
// EPI=0: rate = 0.35*sigmoid((6/7)*(acc + b)) -> g_R fp16
// EPI=1: out  = 0.35*sigmoid(0.75*acc + 0.75*b + 0.125*label) -> out fp32
template<int KDIM, int EPI>
__global__ __launch_bounds__(256, 2)
void k_gemm(const float* __restrict__ bias, const float* __restrict__ label,
            float* __restrict__ out)
{
    const __half* __restrict__ Ag = (EPI == 0) ? g_At : g_R;
    const __half* __restrict__ Bg = (EPI == 0) ? g_Wh : g_Wo;

    __shared__ __align__(1024) uint8_t smA[2][8192];
    __shared__ __align__(1024) uint8_t smB[2][8192];

    const int tid = threadIdx.x, lane = tid & 31, wid = tid >> 5;
    const int m0 = blockIdx.x * 128, n0 = blockIdx.y * 128;
    const int wm0 = (wid >> 2) * 64, wn0 = (wid & 3) * 32;

    // ---- load mapping: each thread cp.asyncs 2 x 16B per tile ----
    const int lrow = tid >> 2, lch = tid & 3;
    const __half* pA0 = Ag + (size_t)(m0 + lrow)      * KDIM + lch * 8;
    const __half* pA1 = Ag + (size_t)(m0 + lrow + 64) * KDIM + lch * 8;
    const __half* pB0 = Bg + (size_t)(n0 + lrow)      * KDIM + lch * 8;
    const __half* pB1 = Bg + (size_t)(n0 + lrow + 64) * KDIM + lch * 8;
    const uint32_t o0 = swoff(lrow, lch), o1 = swoff(lrow + 64, lch);

    uint32_t sA[2] = { su32(smA[0]), su32(smA[1]) };
    uint32_t sB[2] = { su32(smB[0]), su32(smB[1]) };

    // ---- ldmatrix per-thread offsets (within tile), precomputed ----
    uint32_t offA[4][2], offB[2][2];
    {
        const int arow = wm0 + (lane & 15);
        const int ach  = lane >> 4;             // 0/1
        const int brow = wn0 + (lane & 7) + ((lane >> 4) << 3);
        const int bch  = (lane >> 3) & 1;       // 0/1
#pragma unroll
        for (int mt = 0; mt < 4; mt++)
#pragma unroll
            for (int kt = 0; kt < 2; kt++)
                offA[mt][kt] = swoff(arow + mt * 16, kt * 2 + ach);
#pragma unroll
        for (int nt = 0; nt < 2; nt++)
#pragma unroll
            for (int kt = 0; kt < 2; kt++)
                offB[nt][kt] = swoff(brow + nt * 16, kt * 2 + bch);
    }

    float c[4][4][4];
#pragma unroll
    for (int i = 0; i < 4; i++)
#pragma unroll
        for (int j = 0; j < 4; j++)
#pragma unroll
            for (int r = 0; r < 4; r++) c[i][j][r] = 0.0f;

    auto issue = [&](int kc, int s) {
        const size_t ko = (size_t)kc * 32;
        cp16(sA[s] + o0, pA0 + ko); cp16(sA[s] + o1, pA1 + ko);
        cp16(sB[s] + o0, pB0 + ko); cp16(sB[s] + o1, pB1 + ko);
        CP_COMMIT();
    };

    constexpr int NC = KDIM / 32;
    issue(0, 0);
#pragma unroll 1
    for (int kc = 0; kc < NC; kc++) {
        const int s = kc & 1;
        if (kc + 1 < NC) { issue(kc + 1, s ^ 1); CP_WAIT(1); }
        else             { CP_WAIT(0); }
        __syncthreads();
#pragma unroll
        for (int kt = 0; kt < 2; kt++) {
            uint32_t af[4][4], bf[2][4];
#pragma unroll
            for (int mt = 0; mt < 4; mt++) LDSM4(af[mt], sA[s] + offA[mt][kt]);
#pragma unroll
            for (int nt = 0; nt < 2; nt++) LDSM4(bf[nt], sB[s] + offB[nt][kt]);
#pragma unroll
            for (int mt = 0; mt < 4; mt++)
#pragma unroll
                for (int n8 = 0; n8 < 4; n8++)
                    MMA(c[mt][n8], af[mt], bf[n8 >> 1][(n8 & 1) * 2],
                                            bf[n8 >> 1][(n8 & 1) * 2 + 1]);
        }
        __syncthreads();
    }

    // ---- epilogue ----
    const int mrow = m0 + wm0 + (lane >> 2);
    const int ncol = n0 + wn0 + 2 * (lane & 3);
#pragma unroll
    for (int n8 = 0; n8 < 4; n8++) {
        const int n = ncol + n8 * 8;
        const float b0 = bias[n], b1 = bias[n + 1];
#pragma unroll
        for (int mt = 0; mt < 4; mt++) {
            const int m = mrow + mt * 16;
            if (EPI == 0) {
                const float S = 6.0f / 7.0f;
#pragma unroll
                for (int h = 0; h < 2; h++) {   // rows m, m+8
                    const float v0 = S * (c[mt][n8][2 * h]     + b0);
                    const float v1 = S * (c[mt][n8][2 * h + 1] + b1);
                    const __half2 r = __floats2half2_rn(0.35f / (1.0f + __expf(-v0)),
                                                        0.35f / (1.0f + __expf(-v1)));
                    *reinterpret_cast<__half2*>(g_R + (size_t)(m + 8 * h) * HID_SZ + n) = r;
                }
            } else {
#pragma unroll
                for (int h = 0; h < 2; h++) {
                    const int mm = m + 8 * h;
                    const float2 lb = *reinterpret_cast<const float2*>(
                        label + (size_t)mm * OUT_SZ + n);
                    const float v0 = 0.75f * c[mt][n8][2 * h]     + 0.75f * b0 + 0.125f * lb.x;
                    const float v1 = 0.75f * c[mt][n8][2 * h + 1] + 0.75f * b1 + 0.125f * lb.y;
                    float2 o;
                    o.x = 0.35f / (1.0f + __expf(-v0));
                    o.y = 0.35f / (1.0f + __expf(-v1));
                    *reinterpret_cast<float2*>(out + (size_t)mm * OUT_SZ + n) = o;
                }
            }
        }
    }
}

// ---------------- prep: transpose psp[k][b] -> g_At[b][k] fp16 ----------------
__global__ void k_prep_psp(const float* __restrict__ psp) {
    __shared__ float t[32][33];
    const int b0 = blockIdx.x * 32, k0 = blockIdx.y * 32;
    const int tx = threadIdx.x, ty = threadIdx.y;  // (32, 8)
#pragma unroll
    for (int i = 0; i < 32; i += 8)
        t[ty + i][tx] = psp[(size_t)(k0 + ty + i) * B_SZ + b0 + tx];
    __syncthreads();
#pragma unroll
    for (int i = 0; i < 32; i += 8)
        g_At[(size_t)(b0 + ty + i) * IN_SZ + (k0 + tx)] = __float2half_rn(t[tx][ty + i]);
}

// ---------------- prep: fp32 -> fp16 weight conversion ----------------
__global__ void k_cvt(const float4* __restrict__ src, int sel, int n4) {
    const int i = blockIdx.x * 256 + threadIdx.x;
    if (i >= n4) return;
    __half* dst = sel ? g_Wo : g_Wh;
    const float4 v = src[i];
    const __half2 h0 = __floats2half2_rn(v.x, v.y);
    const __half2 h1 = __floats2half2_rn(v.z, v.w);
    uint2 u;
    u.x = *reinterpret_cast<const uint32_t*>(&h0);
    u.y = *reinterpret_cast<const uint32_t*>(&h1);
    *reinterpret_cast<uint2*>(dst + (size_t)i * 4) = u;
}

// ---------------- launcher ----------------
extern "C" void kernel_launch(void* const* d_in, const int* in_sizes, int n_in,
                              void* d_out, int out_size) {
    const float* psp   = (const float*)d_in[0];  // [1024, 4096]
    const float* label = (const float*)d_in[1];  // [4096, 512]
    const float* W_h   = (const float*)d_in[2];  // [2048, 1024]
    const float* b_h   = (const float*)d_in[3];  // [2048]
    const float* W_o   = (const float*)d_in[4];  // [512, 2048]
    const float* b_o   = (const float*)d_in[5];  // [512]
    float* out = (float*)d_out;                  // [4096, 512]

    k_prep_psp<<<dim3(B_SZ / 32, IN_SZ / 32), dim3(32, 8)>>>(psp);
    k_cvt<<<(HID_SZ * IN_SZ / 4 + 255) / 256, 256>>>((const float4*)W_h, 0, HID_SZ * IN_SZ / 4);
    k_cvt<<<(OUT_SZ * HID_SZ / 4 + 255) / 256, 256>>>((const float4*)W_o, 1, OUT_SZ * HID_SZ / 4);

    k_gemm<IN_SZ,  0><<<dim3(B_SZ / 128, HID_SZ / 128), 256>>>(b_h, nullptr, nullptr);
    k_gemm<HID_SZ, 1><<<dim3(B_SZ / 128, OUT_SZ / 128), 256>>>(b_o, label, out);
}

// round 5
// speedup vs baseline: 6.3863x; 1.1334x over previous
#include <cuda_runtime.h>
#include <cuda_fp16.h>
#include <cstdint>

#define B_SZ   4096
#define IN_SZ  1024
#define HID_SZ 2048
#define OUT_SZ 512

// ---------------- scratch (device globals; no allocation) ----------------
__device__ __align__(128) __half g_At[(size_t)B_SZ * IN_SZ];    // psp^T  [B][IN]  fp16
__device__ __align__(128) __half g_Wh[(size_t)HID_SZ * IN_SZ];  // W_h    [HID][IN]
__device__ __align__(128) __half g_Wo[(size_t)OUT_SZ * HID_SZ]; // W_o    [OUT][HID]
__device__ __align__(128) __half g_R [(size_t)B_SZ * HID_SZ];   // rate   [B][HID]

// ---------------- helpers ----------------
__device__ __forceinline__ uint32_t su32(const void* p) {
    uint32_t a;
    asm("{ .reg .u64 t; cvta.to.shared.u64 t, %1; cvt.u32.u64 %0, t; }" : "=r"(a) : "l"(p));
    return a;
}
__device__ __forceinline__ void cp16(uint32_t s, const void* g) {
    asm volatile("cp.async.cg.shared.global [%0], [%1], 16;" :: "r"(s), "l"(g));
}
#define CP_COMMIT()  asm volatile("cp.async.commit_group;")
#define CP_WAIT(N)   asm volatile("cp.async.wait_group %0;" :: "n"(N))

#define LDSM4(r, addr) \
    asm volatile("ldmatrix.sync.aligned.m8n8.x4.shared.b16 {%0,%1,%2,%3}, [%4];" \
        : "=r"((r)[0]), "=r"((r)[1]), "=r"((r)[2]), "=r"((r)[3]) : "r"(addr))

#define MMA(d, a, b0, b1) \
    asm volatile("mma.sync.aligned.m16n8k16.row.col.f32.f16.f16.f32 " \
        "{%0,%1,%2,%3},{%4,%5,%6,%7},{%8,%9},{%0,%1,%2,%3};" \
        : "+f"((d)[0]), "+f"((d)[1]), "+f"((d)[2]), "+f"((d)[3]) \
        : "r"((a)[0]), "r"((a)[1]), "r"((a)[2]), "r"((a)[3]), "r"(b0), "r"(b1))

// ---------------- fused GEMM: 128x128 CTA tile, k-chunk 64, 3-stage cp.async ring ----
// smem tile layout: [128 rows][128 bytes]; chunk swizzle: ch ^= (row & 7)
// EPI=0: rate = 0.35*sigmoid((6/7)*(acc + b)) -> g_R fp16
// EPI=1: out  = 0.35*sigmoid(0.75*acc + 0.75*b + 0.125*label) -> out fp32
template<int KDIM, int EPI>
__global__ __launch_bounds__(256, 2)
void k_gemm(const float* __restrict__ bias, const float* __restrict__ label,
            float* __restrict__ out)
{
    const __half* __restrict__ Ag = (EPI == 0) ? g_At : g_R;
    const __half* __restrict__ Bg = (EPI == 0) ? g_Wh : g_Wo;

    extern __shared__ __align__(1024) uint8_t smem[];   // 3 stages x (16KB A + 16KB B)
    const uint32_t sbase = su32(smem);

    const int tid = threadIdx.x, lane = tid & 31, wid = tid >> 5;
    const int m0 = blockIdx.x * 128, n0 = blockIdx.y * 128;
    const int wm0 = (wid >> 2) * 64, wn0 = (wid & 3) * 32;

    // ---- cp.async mapping: per issue, 4 x 16B for A + 4 x 16B for B ----
    const int lrow = tid >> 3;           // 0..31 (plus 32*j)
    const int lch  = tid & 7;            // 16B chunk in row
    const uint32_t sOff = (uint32_t)(lrow * 128 + ((lch ^ (lrow & 7)) << 4));
    const __half* pA = Ag + (size_t)(m0 + lrow) * KDIM + lch * 8;
    const __half* pB = Bg + (size_t)(n0 + lrow) * KDIM + lch * 8;
    const uint32_t uA = sbase + sOff;            // A at stage offset +0
    const uint32_t uB = sbase + 16384 + sOff;    // B at stage offset +16KB

    // ---- ldmatrix per-thread bases ----
    const int ach = lane >> 4;                                   // A 16B col half
    const int bch = (lane >> 3) & 1;                             // B 16B col half
    uint32_t aBase[4], aSw[4], bBase[2], bSw[2];
#pragma unroll
    for (int mt = 0; mt < 4; mt++) {
        const int r = wm0 + (lane & 15) + mt * 16;
        aBase[mt] = sbase + (uint32_t)(r * 128);
        aSw[mt] = (uint32_t)(r & 7);
    }
#pragma unroll
    for (int nt = 0; nt < 2; nt++) {
        const int r = wn0 + (lane & 7) + ((lane >> 4) << 3) + nt * 16;
        bBase[nt] = sbase + 16384u + (uint32_t)(r * 128);
        bSw[nt] = (uint32_t)(r & 7);
    }

    float c[4][4][4];
#pragma unroll
    for (int i = 0; i < 4; i++)
#pragma unroll
        for (int j = 0; j < 4; j++)
#pragma unroll
            for (int r = 0; r < 4; r++) c[i][j][r] = 0.0f;

    auto issue = [&](int kc, int s) {
        const size_t ko = (size_t)kc * 64;
        const uint32_t so = (uint32_t)s * 32768u;
#pragma unroll
        for (int j = 0; j < 4; j++) {
            cp16(uA + so + j * 4096u, pA + ko + (size_t)j * 32 * KDIM);
            cp16(uB + so + j * 4096u, pB + ko + (size_t)j * 32 * KDIM);
        }
        CP_COMMIT();
    };

    constexpr int NC = KDIM / 64;
    issue(0, 0);
    issue(1, 1);
#pragma unroll 1
    for (int kc = 0; kc < NC; kc++) {
        const int s = kc % 3;
        if (kc + 1 < NC) { CP_WAIT(1); } else { CP_WAIT(0); }
        __syncthreads();                       // stage s ready; stage (kc+2)%3 free
        if (kc + 2 < NC) issue(kc + 2, (kc + 2) % 3);
        const uint32_t so = (uint32_t)s * 32768u;
#pragma unroll
        for (int kt = 0; kt < 4; kt++) {
            uint32_t af[4][4], bf[2][4];
#pragma unroll
            for (int mt = 0; mt < 4; mt++) {
                const uint32_t ch = (uint32_t)(kt * 2 + ach) ^ aSw[mt];
                LDSM4(af[mt], aBase[mt] + so + (ch << 4));
            }
#pragma unroll
            for (int nt = 0; nt < 2; nt++) {
                const uint32_t ch = (uint32_t)(kt * 2 + bch) ^ bSw[nt];
                LDSM4(bf[nt], bBase[nt] + so + (ch << 4));
            }
#pragma unroll
            for (int mt = 0; mt < 4; mt++)
#pragma unroll
                for (int n8 = 0; n8 < 4; n8++)
                    MMA(c[mt][n8], af[mt], bf[n8 >> 1][(n8 & 1) * 2],
                                            bf[n8 >> 1][(n8 & 1) * 2 + 1]);
        }
    }

    // ---- epilogue ----
    const int mrow = m0 + wm0 + (lane >> 2);
    const int ncol = n0 + wn0 + 2 * (lane & 3);
#pragma unroll
    for (int n8 = 0; n8 < 4; n8++) {
        const int n = ncol + n8 * 8;
        const float b0 = bias[n], b1 = bias[n + 1];
#pragma unroll
        for (int mt = 0; mt < 4; mt++) {
            const int m = mrow + mt * 16;
            if (EPI == 0) {
                const float S = 6.0f / 7.0f;
#pragma unroll
                for (int h = 0; h < 2; h++) {   // rows m, m+8
                    const float v0 = S * (c[mt][n8][2 * h]     + b0);
                    const float v1 = S * (c[mt][n8][2 * h + 1] + b1);
                    const __half2 r = __floats2half2_rn(0.35f / (1.0f + __expf(-v0)),
                                                        0.35f / (1.0f + __expf(-v1)));
                    *reinterpret_cast<__half2*>(g_R + (size_t)(m + 8 * h) * HID_SZ + n) = r;
                }
            } else {
#pragma unroll
                for (int h = 0; h < 2; h++) {
                    const int mm = m + 8 * h;
                    const float2 lb = *reinterpret_cast<const float2*>(
                        label + (size_t)mm * OUT_SZ + n);
                    const float v0 = 0.75f * c[mt][n8][2 * h]     + 0.75f * b0 + 0.125f * lb.x;
                    const float v1 = 0.75f * c[mt][n8][2 * h + 1] + 0.75f * b1 + 0.125f * lb.y;
                    float2 o;
                    o.x = 0.35f / (1.0f + __expf(-v0));
                    o.y = 0.35f / (1.0f + __expf(-v1));
                    *reinterpret_cast<float2*>(out + (size_t)mm * OUT_SZ + n) = o;
                }
            }
        }
    }
}

// ---------------- prep: transpose psp[k][b] -> g_At[b][k] fp16 (half2 stores) --------
__global__ void k_prep_psp(const float* __restrict__ psp) {
    __shared__ float t[32][33];                // t[k_local][b_local]
    const int b0 = blockIdx.x * 32, k0 = blockIdx.y * 32;
    const int tx = threadIdx.x, ty = threadIdx.y;  // (32, 8)
    const int tid = ty * 32 + tx;
#pragma unroll
    for (int i = 0; i < 32; i += 8)
        t[ty + i][tx] = psp[(size_t)(k0 + ty + i) * B_SZ + b0 + tx];
    __syncthreads();
    const int kl = (tid & 15) * 2;
#pragma unroll
    for (int r = 0; r < 2; r++) {
        const int bl = (tid >> 4) + r * 16;
        const __half2 h = __floats2half2_rn(t[kl][bl], t[kl + 1][bl]);
        *reinterpret_cast<__half2*>(g_At + (size_t)(b0 + bl) * IN_SZ + k0 + kl) = h;
    }
}

// ---------------- prep: fp32 -> fp16 conversion of both weights, one launch ---------
__global__ void k_cvt_all(const float4* __restrict__ Wh, const float4* __restrict__ Wo) {
    constexpr int N4H = HID_SZ * IN_SZ / 4;   // 524288
    constexpr int N4O = OUT_SZ * HID_SZ / 4;  // 262144
    const int i = blockIdx.x * 256 + threadIdx.x;
    const float4* src;
    __half* dst;
    int idx;
    if (i < N4H)            { src = Wh; dst = g_Wh; idx = i; }
    else if (i < N4H + N4O) { src = Wo; dst = g_Wo; idx = i - N4H; }
    else return;
    const float4 v = src[idx];
    const __half2 h0 = __floats2half2_rn(v.x, v.y);
    const __half2 h1 = __floats2half2_rn(v.z, v.w);
    uint2 u;
    u.x = *reinterpret_cast<const uint32_t*>(&h0);
    u.y = *reinterpret_cast<const uint32_t*>(&h1);
    *reinterpret_cast<uint2*>(dst + (size_t)idx * 4) = u;
}

// ---------------- launcher ----------------
extern "C" void kernel_launch(void* const* d_in, const int* in_sizes, int n_in,
                              void* d_out, int out_size) {
    const float* psp   = (const float*)d_in[0];  // [1024, 4096]
    const float* label = (const float*)d_in[1];  // [4096, 512]
    const float* W_h   = (const float*)d_in[2];  // [2048, 1024]
    const float* b_h   = (const float*)d_in[3];  // [2048]
    const float* W_o   = (const float*)d_in[4];  // [512, 2048]
    const float* b_o   = (const float*)d_in[5];  // [512]
    float* out = (float*)d_out;                  // [4096, 512]

    const int SMEM = 3 * 32768;  // 96KB
    cudaFuncSetAttribute(k_gemm<IN_SZ, 0>,  cudaFuncAttributeMaxDynamicSharedMemorySize, SMEM);
    cudaFuncSetAttribute(k_gemm<HID_SZ, 1>, cudaFuncAttributeMaxDynamicSharedMemorySize, SMEM);

    k_prep_psp<<<dim3(B_SZ / 32, IN_SZ / 32), dim3(32, 8)>>>(psp);
    k_cvt_all<<<(HID_SZ * IN_SZ / 4 + OUT_SZ * HID_SZ / 4 + 255) / 256, 256>>>(
        (const float4*)W_h, (const float4*)W_o);

    k_gemm<IN_SZ,  0><<<dim3(B_SZ / 128, HID_SZ / 128), 256, SMEM>>>(b_h, nullptr, nullptr);
    k_gemm<HID_SZ, 1><<<dim3(B_SZ / 128, OUT_SZ / 128), 256, SMEM>>>(b_o, label, out);
}

// round 6
// speedup vs baseline: 6.9304x; 1.0852x over previous
#include <cuda_runtime.h>
#include <cuda_fp16.h>
#include <cstdint>

#define B_SZ   4096
#define IN_SZ  1024
#define HID_SZ 2048
#define OUT_SZ 512

// ---------------- scratch (device globals; no allocation) ----------------
__device__ __align__(128) __half g_At[(size_t)B_SZ * IN_SZ];    // psp^T  [B][IN]  fp16
__device__ __align__(128) __half g_Wh[(size_t)HID_SZ * IN_SZ];  // W_h    [HID][IN]
__device__ __align__(128) __half g_Wo[(size_t)OUT_SZ * HID_SZ]; // W_o    [OUT][HID]
__device__ __align__(128) __half g_R [(size_t)B_SZ * HID_SZ];   // rate   [B][HID]

// ---------------- helpers ----------------
__device__ __forceinline__ uint32_t su32(const void* p) {
    uint32_t a;
    asm("{ .reg .u64 t; cvta.to.shared.u64 t, %1; cvt.u32.u64 %0, t; }" : "=r"(a) : "l"(p));
    return a;
}
__device__ __forceinline__ void cp16(uint32_t s, const void* g) {
    asm volatile("cp.async.cg.shared.global [%0], [%1], 16;" :: "r"(s), "l"(g));
}
#define CP_COMMIT()  asm volatile("cp.async.commit_group;")
#define CP_WAIT(N)   asm volatile("cp.async.wait_group %0;" :: "n"(N))

#define LDSM4(r, addr) \
    asm volatile("ldmatrix.sync.aligned.m8n8.x4.shared.b16 {%0,%1,%2,%3}, [%4];" \
        : "=r"((r)[0]), "=r"((r)[1]), "=r"((r)[2]), "=r"((r)[3]) : "r"(addr))

#define MMA(d, a, b0, b1) \
    asm volatile("mma.sync.aligned.m16n8k16.row.col.f32.f16.f16.f32 " \
        "{%0,%1,%2,%3},{%4,%5,%6,%7},{%8,%9},{%0,%1,%2,%3};" \
        : "+f"((d)[0]), "+f"((d)[1]), "+f"((d)[2]), "+f"((d)[3]) \
        : "r"((a)[0]), "r"((a)[1]), "r"((a)[2]), "r"((a)[3]), "r"(b0), "r"(b1))

// ---------------- fused GEMM: MTx128 CTA tile, k-chunk 64, 3-stage cp.async ring ----
// smem tile layout: [rows][128 bytes]; 16B-chunk swizzle: ch ^= (row & 7)
// Warps: 2 (m) x 4 (n). Warp tile: (MT/2) x 32.
// EPI=0: rate = 0.35*sigmoid((6/7)*(acc + b)) -> g_R fp16
// EPI=1: out  = 0.35*sigmoid(0.75*acc + 0.75*b + 0.125*label) -> out fp32
template<int KDIM, int EPI, int MT>
__global__ __launch_bounds__(256, 2)
void k_gemm(const float* __restrict__ bias, const float* __restrict__ label,
            float* __restrict__ out)
{
    constexpr int NMT = MT / 32;                       // per-warp m16 tiles
    constexpr uint32_t BOFF  = (uint32_t)MT * 128u;    // B tile offset in stage
    constexpr uint32_t STAGE = BOFF + 16384u;          // stage size

    const __half* __restrict__ Ag = (EPI == 0) ? g_At : g_R;
    const __half* __restrict__ Bg = (EPI == 0) ? g_Wh : g_Wo;

    extern __shared__ __align__(1024) uint8_t smem[];
    const uint32_t sbase = su32(smem);

    const int tid = threadIdx.x, lane = tid & 31, wid = tid >> 5;
    const int m0 = blockIdx.x * MT, n0 = blockIdx.y * 128;
    const int wm0 = (wid >> 2) * (MT / 2), wn0 = (wid & 3) * 32;

    // ---- cp.async mapping ----
    const int lrow = tid >> 3;           // 0..31 (plus 32*j)
    const int lch  = tid & 7;            // 16B chunk in row
    const uint32_t sOff = (uint32_t)(lrow * 128 + ((lch ^ (lrow & 7)) << 4));
    const __half* pA = Ag + (size_t)(m0 + lrow) * KDIM + lch * 8;
    const __half* pB = Bg + (size_t)(n0 + lrow) * KDIM + lch * 8;
    const uint32_t uA = sbase + sOff;
    const uint32_t uB = sbase + BOFF + sOff;

    // ---- ldmatrix per-thread bases ----
    const int ach = lane >> 4;
    const int bch = (lane >> 3) & 1;
    uint32_t aBase[NMT], aSw[NMT], bBase[2], bSw[2];
#pragma unroll
    for (int mt = 0; mt < NMT; mt++) {
        const int r = wm0 + (lane & 15) + mt * 16;
        aBase[mt] = sbase + (uint32_t)(r * 128);
        aSw[mt] = (uint32_t)(r & 7);
    }
#pragma unroll
    for (int nt = 0; nt < 2; nt++) {
        const int r = wn0 + (lane & 7) + ((lane >> 4) << 3) + nt * 16;
        bBase[nt] = sbase + BOFF + (uint32_t)(r * 128);
        bSw[nt] = (uint32_t)(r & 7);
    }

    float c[NMT][4][4];
#pragma unroll
    for (int i = 0; i < NMT; i++)
#pragma unroll
        for (int j = 0; j < 4; j++)
#pragma unroll
            for (int r = 0; r < 4; r++) c[i][j][r] = 0.0f;

    auto issue = [&](int kc, int s) {
        const size_t ko = (size_t)kc * 64;
        const uint32_t so = (uint32_t)s * STAGE;
#pragma unroll
        for (int j = 0; j < MT / 32; j++)
            cp16(uA + so + j * 4096u, pA + ko + (size_t)j * 32 * KDIM);
#pragma unroll
        for (int j = 0; j < 4; j++)
            cp16(uB + so + j * 4096u, pB + ko + (size_t)j * 32 * KDIM);
        CP_COMMIT();
    };

    constexpr int NC = KDIM / 64;
    issue(0, 0);
    issue(1, 1);
#pragma unroll 1
    for (int kc = 0; kc < NC; kc++) {
        const int s = kc % 3;
        if (kc + 1 < NC) { CP_WAIT(1); } else { CP_WAIT(0); }
        __syncthreads();                      // stage s ready; stage (kc+2)%3 free
        if (kc + 2 < NC) issue(kc + 2, (kc + 2) % 3);
        const uint32_t so = (uint32_t)s * STAGE;
#pragma unroll
        for (int kt = 0; kt < 4; kt++) {
            uint32_t af[NMT][4], bf[2][4];
#pragma unroll
            for (int mt = 0; mt < NMT; mt++) {
                const uint32_t ch = (uint32_t)(kt * 2 + ach) ^ aSw[mt];
                LDSM4(af[mt], aBase[mt] + so + (ch << 4));
            }
#pragma unroll
            for (int nt = 0; nt < 2; nt++) {
                const uint32_t ch = (uint32_t)(kt * 2 + bch) ^ bSw[nt];
                LDSM4(bf[nt], bBase[nt] + so + (ch << 4));
            }
#pragma unroll
            for (int mt = 0; mt < NMT; mt++)
#pragma unroll
                for (int n8 = 0; n8 < 4; n8++)
                    MMA(c[mt][n8], af[mt], bf[n8 >> 1][(n8 & 1) * 2],
                                            bf[n8 >> 1][(n8 & 1) * 2 + 1]);
        }
    }

    // ---- epilogue ----
    const int mrow = m0 + wm0 + (lane >> 2);
    const int ncol = n0 + wn0 + 2 * (lane & 3);
#pragma unroll
    for (int n8 = 0; n8 < 4; n8++) {
        const int n = ncol + n8 * 8;
        const float b0 = bias[n], b1 = bias[n + 1];
#pragma unroll
        for (int mt = 0; mt < NMT; mt++) {
            const int m = mrow + mt * 16;
            if (EPI == 0) {
                const float S = 6.0f / 7.0f;
#pragma unroll
                for (int h = 0; h < 2; h++) {   // rows m, m+8
                    const float v0 = S * (c[mt][n8][2 * h]     + b0);
                    const float v1 = S * (c[mt][n8][2 * h + 1] + b1);
                    const __half2 r = __floats2half2_rn(0.35f / (1.0f + __expf(-v0)),
                                                        0.35f / (1.0f + __expf(-v1)));
                    *reinterpret_cast<__half2*>(g_R + (size_t)(m + 8 * h) * HID_SZ + n) = r;
                }
            } else {
#pragma unroll
                for (int h = 0; h < 2; h++) {
                    const int mm = m + 8 * h;
                    const float2 lb = *reinterpret_cast<const float2*>(
                        label + (size_t)mm * OUT_SZ + n);
                    const float v0 = 0.75f * c[mt][n8][2 * h]     + 0.75f * b0 + 0.125f * lb.x;
                    const float v1 = 0.75f * c[mt][n8][2 * h + 1] + 0.75f * b1 + 0.125f * lb.y;
                    float2 o;
                    o.x = 0.35f / (1.0f + __expf(-v0));
                    o.y = 0.35f / (1.0f + __expf(-v1));
                    *reinterpret_cast<float2*>(out + (size_t)mm * OUT_SZ + n) = o;
                }
            }
        }
    }
}

// ---------------- prep (single launch): psp transpose + both weight converts --------
__global__ void k_prep(const float* __restrict__ psp,
                       const float4* __restrict__ Wh, const float4* __restrict__ Wo) {
    constexpr int NT_BLK = (B_SZ / 32) * (IN_SZ / 32);   // 4096 transpose blocks
    constexpr int N4H = HID_SZ * IN_SZ / 4;              // 524288
    constexpr int N4O = OUT_SZ * HID_SZ / 4;             // 262144
    const int bid = blockIdx.x, tid = threadIdx.x;

    if (bid < NT_BLK) {
        __shared__ float t[32][33];                      // t[k_local][b_local]
        const int b0 = (bid % (B_SZ / 32)) * 32;
        const int k0 = (bid / (B_SZ / 32)) * 32;
        const int tx = tid & 31, ty = tid >> 5;          // (32, 8)
#pragma unroll
        for (int i = 0; i < 32; i += 8)
            t[ty + i][tx] = psp[(size_t)(k0 + ty + i) * B_SZ + b0 + tx];
        __syncthreads();
        const int kl = (tid & 15) * 2;
#pragma unroll
        for (int r = 0; r < 2; r++) {
            const int bl = (tid >> 4) + r * 16;
            const __half2 h = __floats2half2_rn(t[kl][bl], t[kl + 1][bl]);
            *reinterpret_cast<__half2*>(g_At + (size_t)(b0 + bl) * IN_SZ + k0 + kl) = h;
        }
        return;
    }
    const int i = (bid - NT_BLK) * 256 + tid;
    const float4* src;
    __half* dst;
    int idx;
    if (i < N4H)            { src = Wh; dst = g_Wh; idx = i; }
    else if (i < N4H + N4O) { src = Wo; dst = g_Wo; idx = i - N4H; }
    else return;
    const float4 v = src[idx];
    const __half2 h0 = __floats2half2_rn(v.x, v.y);
    const __half2 h1 = __floats2half2_rn(v.z, v.w);
    uint2 u;
    u.x = *reinterpret_cast<const uint32_t*>(&h0);
    u.y = *reinterpret_cast<const uint32_t*>(&h1);
    *reinterpret_cast<uint2*>(dst + (size_t)idx * 4) = u;
}

// ---------------- launcher ----------------
extern "C" void kernel_launch(void* const* d_in, const int* in_sizes, int n_in,
                              void* d_out, int out_size) {
    const float* psp   = (const float*)d_in[0];  // [1024, 4096]
    const float* label = (const float*)d_in[1];  // [4096, 512]
    const float* W_h   = (const float*)d_in[2];  // [2048, 1024]
    const float* b_h   = (const float*)d_in[3];  // [2048]
    const float* W_o   = (const float*)d_in[4];  // [512, 2048]
    const float* b_o   = (const float*)d_in[5];  // [512]
    float* out = (float*)d_out;                  // [4096, 512]

    const int SMEM1 = 3 * (128 * 128 + 16384);   // 98304
    const int SMEM2 = 3 * (64 * 128 + 16384);    // 73728
    cudaFuncSetAttribute(k_gemm<IN_SZ, 0, 128>, cudaFuncAttributeMaxDynamicSharedMemorySize, SMEM1);
    cudaFuncSetAttribute(k_gemm<HID_SZ, 1, 64>, cudaFuncAttributeMaxDynamicSharedMemorySize, SMEM2);

    const int PREP_BLOCKS = (B_SZ / 32) * (IN_SZ / 32)
                          + (HID_SZ * IN_SZ / 4 + OUT_SZ * HID_SZ / 4 + 255) / 256;
    k_prep<<<PREP_BLOCKS, 256>>>(psp, (const float4*)W_h, (const float4*)W_o);

    k_gemm<IN_SZ,  0, 128><<<dim3(B_SZ / 128, HID_SZ / 128), 256, SMEM1>>>(b_h, nullptr, nullptr);
    k_gemm<HID_SZ, 1, 64 ><<<dim3(B_SZ / 64,  OUT_SZ / 128), 256, SMEM2>>>(b_o, label, out);
}